// round 5
// baseline (speedup 1.0000x reference)
#include <cuda_runtime.h>
#include <cstdint>
#include <math.h>

#define Yx   256
#define TP1  513
#define Tt   512
#define MAT  (TP1 * Yx * Yx)   // 33,619,968
#define STAGES 5
#define STAGEF 8192            // floats per stage (256*32)

// ---------------- scratch (static device globals; no allocation) ----------
__device__ __align__(16) float g_Mexp[MAT];
__device__ float g_alpha[(TP1 + 1) * Yx];
__device__ float g_beta [(TP1 + 1) * Yx];
__device__ float g_sA[TP1];
__device__ float g_sB[TP1];
__device__ float g_Ap[TP1 * Yx];
__device__ __align__(16) unsigned char g_idx[(Tt - 1) * Yx];
__device__ float g_dfin[Yx];

// ---------------- helpers -------------------------------------------------
__device__ __forceinline__ unsigned smem_u32(const void* p) {
    return (unsigned)__cvta_generic_to_shared(p);
}
__device__ __forceinline__ unsigned mapaTo(unsigned saddr, unsigned peer) {
    unsigned ra;
    asm volatile("mapa.shared::cluster.u32 %0, %1, %2;" : "=r"(ra) : "r"(saddr), "r"(peer));
    return ra;
}
__device__ __forceinline__ void stCl(unsigned ra, float v) {
    asm volatile("st.shared::cluster.f32 [%0], %1;" :: "r"(ra), "f"(v) : "memory");
}
__device__ __forceinline__ void arriveRel(unsigned ra) {
    asm volatile("mbarrier.arrive.release.cluster.shared::cluster.b64 _, [%0];" :: "r"(ra) : "memory");
}
__device__ __forceinline__ void mbarWait(unsigned addr, unsigned parity) {
    asm volatile(
        "{\n\t.reg .pred p;\n\t"
        "WL_%=:\n\t"
        "mbarrier.try_wait.parity.acquire.cluster.shared::cta.b64 p, [%0], %1;\n\t"
        "@!p bra WL_%=;\n\t}"
        :: "r"(addr), "r"(parity) : "memory");
}
__device__ __forceinline__ void clusterSync() {
    asm volatile("barrier.cluster.arrive.aligned;" ::: "memory");
    asm volatile("barrier.cluster.wait.aligned;"   ::: "memory");
}
__device__ __forceinline__ void cp16(unsigned dst, const float* src) {
    asm volatile("cp.async.cg.shared.global [%0], [%1], 16;" :: "r"(dst), "l"(src) : "memory");
}
__device__ __forceinline__ void cpCommit() {
    asm volatile("cp.async.commit_group;" ::: "memory");
}
__device__ __forceinline__ void cpWait4() {
    asm volatile("cp.async.wait_group 4;" ::: "memory");
}
__device__ __forceinline__ float warpSum(float v) {
#pragma unroll
    for (int o = 16; o; o >>= 1) v += __shfl_down_sync(0xffffffffu, v, o);
    return v;
}
__device__ __forceinline__ float warpAllSum(float v) {
#pragma unroll
    for (int o = 16; o; o >>= 1) v += __shfl_xor_sync(0xffffffffu, v, o);
    return v;
}
__device__ __forceinline__ float warpMax(float v) {
#pragma unroll
    for (int o = 16; o; o >>= 1) v = fmaxf(v, __shfl_down_sync(0xffffffffu, v, o));
    return v;
}

// ---------------- K1: Mexp = exp(sum_k w_k f_k) with boundary masks -------
__global__ void kM(const float* __restrict__ f, const float* __restrict__ w) {
    size_t lin = ((size_t)blockIdx.x * blockDim.x + threadIdx.x) * 4;
    float w0 = __ldg(w + 0), w1 = __ldg(w + 1), w2 = __ldg(w + 2), w3 = __ldg(w + 3);
    const float4 a = *(const float4*)(f + lin);
    const float4 b = *(const float4*)(f + lin + (size_t)MAT);
    const float4 c = *(const float4*)(f + lin + 2ull * MAT);
    const float4 d = *(const float4*)(f + lin + 3ull * MAT);
    int t  = (int)(lin >> 16);
    int i  = (int)(lin >> 8) & 255;
    int j0 = (int)lin & 255;
    float v0 = w0 * a.x + w1 * b.x + w2 * c.x + w3 * d.x;
    float v1 = w0 * a.y + w1 * b.y + w2 * c.y + w3 * d.y;
    float v2 = w0 * a.z + w1 * b.z + w2 * c.z + w3 * d.z;
    float v3 = w0 * a.w + w1 * b.w + w2 * c.w + w3 * d.w;
    bool mrow = (t == 0 && i != 0);
    float4 o;
    o.x = (mrow || (t == Tt && (j0 + 0) != 0)) ? 0.f : expf(v0);
    o.y = (mrow || (t == Tt && (j0 + 1) != 0)) ? 0.f : expf(v1);
    o.z = (mrow || (t == Tt && (j0 + 2) != 0)) ? 0.f : expf(v2);
    o.w = (mrow || (t == Tt && (j0 + 3) != 0)) ? 0.f : expf(v3);
    *(float4*)(g_Mexp + lin) = o;
}

// ---------------- stage fill helpers (coalesced cp.async) -----------------
// forward/viterbi slice: all 256 rows x cols [32r, 32r+32), stage layout [row][32]
__device__ __forceinline__ void issueCols(unsigned stBase, int slot, int tm, int rank, int tid) {
    const float* src = g_Mexp + (size_t)tm * 65536 + 32 * rank;
    unsigned dst = stBase + (unsigned)slot * STAGEF * 4;
#pragma unroll
    for (int i = 0; i < 8; i++) {
        int q = tid + 256 * i;           // float4 index
        int row = q >> 3, c4 = q & 7;
        cp16(dst + (unsigned)q * 16, src + (size_t)row * 256 + c4 * 4);
    }
}
// backward slice: rows [32r, 32r+32) x all cols, contiguous 32KB, layout [32][256]
__device__ __forceinline__ void issueRows(unsigned stBase, int slot, int tm, int rank, int tid) {
    const float* src = g_Mexp + (size_t)tm * 65536 + (size_t)(32 * rank) * 256;
    unsigned dst = stBase + (unsigned)slot * STAGEF * 4;
#pragma unroll
    for (int i = 0; i < 8; i++) {
        int q = tid + 256 * i;
        cp16(dst + (unsigned)q * 16, src + (size_t)q * 4);
    }
}

// ---------------- K2: three scans, one cluster each -----------------------
extern __shared__ float dynStage[];   // STAGES * 8192 floats
__global__ void __cluster_dims__(8, 1, 1) __launch_bounds__(256, 1) kScan() {
    __shared__ float sCur[Yx];
    __shared__ float sInc[2][Yx];
    __shared__ float sPs[2][8];
    __shared__ float sRed[Yx];
    __shared__ int   sRedI[Yx];
    __shared__ float sInitMax;
    __shared__ __align__(8) unsigned long long mbarS;

    const int tid  = threadIdx.x;
    const int role = blockIdx.x >> 3;
    const int rank = blockIdx.x & 7;
    const int lane = tid & 31;
    const int wid  = tid >> 5;
    const unsigned stBase   = smem_u32(dynStage);
    const unsigned incBase  = smem_u32(&sInc[0][0]);
    const unsigned psBase   = smem_u32(&sPs[0][0]);
    const unsigned mbarAddr = smem_u32(&mbarS);

    if (tid == 0)
        asm volatile("mbarrier.init.shared.b64 [%0], %1;" :: "r"(mbarAddr), "r"(256) : "memory");

    // precompute remote addresses
    unsigned rInc[8], rPs[8], rBar[8];
#pragma unroll
    for (int p = 0; p < 8; p++) {
        rInc[p] = mapaTo(incBase, p);
        rPs[p]  = mapaTo(psBase, p);
        rBar[p] = mapaTo(mbarAddr, p);
    }

    if (role == 0) {
        // ============== forward scan ==============
        sCur[tid] = (tid == 0) ? 1.f : 0.f;
        if (tid < 32) g_alpha[32 * rank + tid] = (32 * rank + tid == 0) ? 1.f : 0.f;
        __syncthreads();
        clusterSync();
#pragma unroll
        for (int s = 0; s < STAGES; s++) { issueCols(stBase, s, s, rank, tid); cpCommit(); }
        for (int t = 0; t < TP1; t++) {
            const int buf = t & 1;
            cpWait4();
            __syncthreads();                         // stage ready + sCur visible
            const float* st = dynStage + (t % STAGES) * STAGEF;
            const int kb = wid * 32;
            float a0 = 0.f, a1 = 0.f, a2 = 0.f, a3 = 0.f;
#pragma unroll
            for (int kk = 0; kk < 32; kk += 4) {
                a0 += st[(kb + kk + 0) * 32 + lane] * sCur[kb + kk + 0];
                a1 += st[(kb + kk + 1) * 32 + lane] * sCur[kb + kk + 1];
                a2 += st[(kb + kk + 2) * 32 + lane] * sCur[kb + kk + 2];
                a3 += st[(kb + kk + 3) * 32 + lane] * sCur[kb + kk + 3];
            }
            sRed[tid] = (a0 + a1) + (a2 + a3);
            __syncthreads();
            if (tid < 32) {
                float raw = 0.f;
#pragma unroll
                for (int g = 0; g < 8; g++) raw += sRed[g * 32 + tid];
                float ps = warpSum(raw);
                unsigned off = (unsigned)(buf * Yx + 32 * rank + tid) * 4;
#pragma unroll
                for (int p = 0; p < 8; p++) stCl(rInc[p] + off, raw);
                if (tid == 0) {
                    unsigned po = (unsigned)(buf * 8 + rank) * 4;
#pragma unroll
                    for (int p = 0; p < 8; p++) stCl(rPs[p] + po, ps);
                }
#pragma unroll
                for (int p = 0; p < 8; p++) arriveRel(rBar[p]);
            }
            int tn = t + STAGES;
            if (tn < TP1) issueCols(stBase, tn % STAGES, tn, rank, tid);
            cpCommit();
            mbarWait(mbarAddr, (unsigned)buf);
            float s = 0.f;
#pragma unroll
            for (int p = 0; p < 8; p++) s += sPs[buf][p];
            float inv = 1.f / s;
            sCur[tid] = sInc[buf][tid] * inv;
            if (tid < 32)
                g_alpha[(size_t)(t + 1) * Yx + 32 * rank + tid] = sInc[buf][32 * rank + tid] * inv;
            if (rank == 0 && tid == 0) g_sA[t] = s;
        }
        clusterSync();
    } else if (role == 1) {
        // ============== backward scan ==============
        sCur[tid] = (tid == 0) ? 1.f : 0.f;
        if (tid < 32) g_beta[(size_t)513 * Yx + 32 * rank + tid] = (32 * rank + tid == 0) ? 1.f : 0.f;
        __syncthreads();
        clusterSync();
#pragma unroll
        for (int s = 0; s < STAGES; s++) { issueRows(stBase, s, Tt - s, rank, tid); cpCommit(); }
        for (int idx = 0; idx < TP1; idx++) {
            const int t = Tt - idx;
            const int buf = idx & 1;
            cpWait4();
            __syncthreads();
            const float* st = dynStage + (idx % STAGES) * STAGEF;
            const int rb = wid * 4;
            float a0 = 0.f, a1 = 0.f, a2 = 0.f, a3 = 0.f;
#pragma unroll
            for (int jb = 0; jb < 8; jb++) {
                float cv = sCur[jb * 32 + lane];
                a0 += st[(rb + 0) * 256 + jb * 32 + lane] * cv;
                a1 += st[(rb + 1) * 256 + jb * 32 + lane] * cv;
                a2 += st[(rb + 2) * 256 + jb * 32 + lane] * cv;
                a3 += st[(rb + 3) * 256 + jb * 32 + lane] * cv;
            }
            a0 = warpAllSum(a0); a1 = warpAllSum(a1);
            a2 = warpAllSum(a2); a3 = warpAllSum(a3);
            if (lane == 0) sRed[wid] = (a0 + a1) + (a2 + a3);
            __syncthreads();
            if (lane < 4) {
                float v = (lane == 0) ? a0 : (lane == 1) ? a1 : (lane == 2) ? a2 : a3;
                if (tid == 0) {
                    float ps = 0.f;
#pragma unroll
                    for (int g = 0; g < 8; g++) ps += sRed[g];
                    unsigned po = (unsigned)(buf * 8 + rank) * 4;
#pragma unroll
                    for (int p = 0; p < 8; p++) stCl(rPs[p] + po, ps);
                }
                unsigned off = (unsigned)(buf * Yx + 32 * rank + rb + lane) * 4;
#pragma unroll
                for (int p = 0; p < 8; p++) stCl(rInc[p] + off, v);
#pragma unroll
                for (int p = 0; p < 8; p++) arriveRel(rBar[p]);
            }
            int tm = t - STAGES;
            if (tm >= 0) issueRows(stBase, (idx + STAGES) % STAGES, tm, rank, tid);
            cpCommit();
            mbarWait(mbarAddr, (unsigned)buf);
            float s = 0.f;
#pragma unroll
            for (int p = 0; p < 8; p++) s += sPs[buf][p];
            float inv = 1.f / s;
            sCur[tid] = sInc[buf][tid] * inv;
            if (tid < 32)
                g_beta[(size_t)t * Yx + 32 * rank + tid] = sInc[buf][32 * rank + tid] * inv;
            if (rank == 0 && tid == 0) g_sB[t] = s;
        }
        clusterSync();
    } else {
        // ============== viterbi (max-times) ==============
        float v0 = g_Mexp[tid];                 // Mexp[0][0][tid]
        sRed[tid] = v0;
        __syncthreads();
        if (tid < 32) {
            float mx = sRed[tid];
#pragma unroll
            for (int g = 1; g < 8; g++) mx = fmaxf(mx, sRed[g * 32 + tid]);
            mx = warpMax(mx);
            if (tid == 0) sInitMax = mx;
        }
        __syncthreads();
        sCur[tid] = v0 / sInitMax;
        __syncthreads();
        clusterSync();
#pragma unroll
        for (int s = 0; s < STAGES; s++) { issueCols(stBase, s, 1 + s, rank, tid); cpCommit(); }
        for (int t = 1; t < Tt; t++) {
            const int idx = t - 1;
            const int buf = idx & 1;
            cpWait4();
            __syncthreads();
            const float* st = dynStage + (idx % STAGES) * STAGEF;
            const int kb = wid * 32;
            // 4 contiguous chains (ties keep lowest index within & across chains)
            float bv[4]; int bi[4];
#pragma unroll
            for (int c = 0; c < 4; c++) { bv[c] = -1.f; bi[c] = 0; }
#pragma unroll
            for (int c = 0; c < 4; c++) {
#pragma unroll
                for (int kk = 0; kk < 8; kk++) {
                    int k = c * 8 + kk;
                    float p = st[(kb + k) * 32 + lane] * sCur[kb + k];
                    if (p > bv[c]) { bv[c] = p; bi[c] = kb + k; }
                }
            }
            float best = bv[0]; int bidx = bi[0];
#pragma unroll
            for (int c = 1; c < 4; c++) if (bv[c] > best) { best = bv[c]; bidx = bi[c]; }
            sRed[tid] = best; sRedI[tid] = bidx;
            __syncthreads();
            if (tid < 32) {
                float b = sRed[tid]; int ix = sRedI[tid];
#pragma unroll
                for (int g = 1; g < 8; g++) {
                    float vv = sRed[g * 32 + tid];
                    if (vv > b) { b = vv; ix = sRedI[g * 32 + tid]; }
                }
                g_idx[(size_t)(t - 1) * Yx + 32 * rank + tid] = (unsigned char)ix;
                float pm = warpMax(b);
                unsigned off = (unsigned)(buf * Yx + 32 * rank + tid) * 4;
#pragma unroll
                for (int p = 0; p < 8; p++) stCl(rInc[p] + off, b);
                if (tid == 0) {
                    unsigned po = (unsigned)(buf * 8 + rank) * 4;
#pragma unroll
                    for (int p = 0; p < 8; p++) stCl(rPs[p] + po, pm);
                }
#pragma unroll
                for (int p = 0; p < 8; p++) arriveRel(rBar[p]);
            }
            int tn = t + STAGES;
            if (tn < Tt) issueCols(stBase, (idx + STAGES) % STAGES, tn, rank, tid);
            cpCommit();
            mbarWait(mbarAddr, (unsigned)buf);
            float s = sPs[buf][0];
#pragma unroll
            for (int p = 1; p < 8; p++) s = fmaxf(s, sPs[buf][p]);
            float inv = 1.f / s;
            sCur[tid] = sInc[buf][tid] * inv;   // uniform scale: argmax preserved
        }
        if (rank == 0) g_dfin[tid] = sCur[tid];
        clusterSync();
    }
}

// ---------------- K3: log-scale prefix sums (double), Ap, backtrack -------
extern __shared__ unsigned char sdyn[];
__global__ void kFinish(float* __restrict__ dout, int writePath) {
    double* sLA = (double*)sdyn;                 // [514]
    double* sLB = sLA + 514;                     // [514]
    unsigned char* sIdx = (unsigned char*)(sLB + 514); // [511*256]
    int tid = threadIdx.x;

    {
        const uint4* src = (const uint4*)g_idx;
        uint4* dst = (uint4*)sIdx;
        for (int i = tid; i < (511 * 256) / 16; i += 256) dst[i] = src[i];
    }
    for (int t = tid; t < 513; t += 256) {
        sLA[t + 1] = log((double)g_sA[t]);
        sLB[t]     = log((double)g_sB[t]);
    }
    if (tid == 0) { sLA[0] = 0.0; sLB[513] = 0.0; }
    __syncthreads();
    if (tid == 0) {
        double r = 0.0;
        for (int t = 1; t <= 513; t++) { r += sLA[t]; sLA[t] = r; }
    } else if (tid == 32) {
        double r = 0.0;
        for (int t = 512; t >= 0; t--) { r += sLB[t]; sLB[t] = r; }
    } else if (tid == 64 && writePath) {
        float best = g_dfin[0]; int last = 0;
        for (int j = 1; j < 256; j++) { float v = g_dfin[j]; if (v > best) { best = v; last = j; } }
        float* pout = dout + (size_t)MAT;
        pout[511] = (float)last;
        int y = last;
        for (int r = 510; r >= 0; r--) { y = sIdx[r * 256 + y]; pout[r] = (float)y; }
    }
    __syncthreads();
    double lz = sLA[513];
    for (int t = 0; t < 513; t++) {
        float Fv = expf((float)(sLA[t] + sLB[t + 1] - lz));
        g_Ap[t * 256 + tid] = g_alpha[t * 256 + tid] * Fv;
    }
}

// ---------------- K4: p12 = Ap[t][i] * Mexp * beta[t+1][j] ----------------
__global__ void kP12(float* __restrict__ dout) {
    size_t lin = ((size_t)blockIdx.x * blockDim.x + threadIdx.x) * 4;
    int t = (int)(lin >> 16);
    int i = (int)(lin >> 8) & 255;
    int j = (int)lin & 255;
    float4 mv = *(const float4*)(g_Mexp + lin);
    float  a  = g_Ap[t * 256 + i];
    float4 bv = *(const float4*)(g_beta + (size_t)(t + 1) * 256 + j);
    float4 o;
    o.x = a * mv.x * bv.x;
    o.y = a * mv.y * bv.y;
    o.z = a * mv.z * bv.z;
    o.w = a * mv.w * bv.w;
    *(float4*)(dout + lin) = o;
}

// ---------------- launch ---------------------------------------------------
extern "C" void kernel_launch(void* const* d_in, const int* in_sizes, int n_in,
                              void* d_out, int out_size) {
    const float* f = (const float*)d_in[0];
    const float* w = (const float*)d_in[1];
    if (n_in >= 2 && in_sizes[0] == 4) {
        f = (const float*)d_in[1];
        w = (const float*)d_in[0];
    }
    float* out = (float*)d_out;
    int writePath = (out_size >= MAT + 512) ? 1 : 0;

    const int SCAN_SMEM = STAGES * STAGEF * 4;     // 163,840 B dynamic
    const int FIN_SMEM  = 514 * 8 * 2 + 511 * 256; // 139,040 B
    cudaFuncSetAttribute(kScan,   cudaFuncAttributeMaxDynamicSharedMemorySize, SCAN_SMEM);
    cudaFuncSetAttribute(kFinish, cudaFuncAttributeMaxDynamicSharedMemorySize, FIN_SMEM);

    kM<<<32832, 256>>>(f, w);
    kScan<<<24, 256, SCAN_SMEM>>>();
    kFinish<<<1, 256, FIN_SMEM>>>(out, writePath);
    kP12<<<32832, 256>>>(out);
}

// round 7
// speedup vs baseline: 1.2258x; 1.2258x over previous
#include <cuda_runtime.h>
#include <cstdint>
#include <math.h>

#define Yx   256
#define TP1  513
#define Tt   512
#define MAT  (TP1 * Yx * Yx)   // 33,619,968

// ---------------- scratch (static device globals; no allocation) ----------
__device__ __align__(16) float g_Mexp[MAT];
__device__ float g_alpha[(TP1 + 1) * Yx];
__device__ float g_beta [(TP1 + 1) * Yx];
__device__ float g_sA[TP1];
__device__ float g_sB[TP1];
__device__ float g_F[TP1];                              // exp(LA[t]+LB[t+1]-logZ)
__device__ __align__(16) unsigned char g_idx[(Tt - 1) * Yx];
__device__ float g_dfin[Yx];

// ---------------- helpers -------------------------------------------------
__device__ __forceinline__ unsigned smem_u32(const void* p) {
    return (unsigned)__cvta_generic_to_shared(p);
}
__device__ __forceinline__ unsigned mapaTo(unsigned saddr, unsigned peer) {
    unsigned ra;
    asm volatile("mapa.shared::cluster.u32 %0, %1, %2;" : "=r"(ra) : "r"(saddr), "r"(peer));
    return ra;
}
__device__ __forceinline__ void stCl(unsigned ra, float v) {
    asm volatile("st.shared::cluster.f32 [%0], %1;" :: "r"(ra), "f"(v) : "memory");
}
__device__ __forceinline__ void mbarInit(unsigned addr, unsigned cnt) {
    asm volatile("mbarrier.init.shared.b64 [%0], %1;" :: "r"(addr), "r"(cnt) : "memory");
}
__device__ __forceinline__ void arriveRel(unsigned ra) {
    asm volatile("mbarrier.arrive.release.cluster.shared::cluster.b64 _, [%0];" :: "r"(ra) : "memory");
}
__device__ __forceinline__ void mbarWait(unsigned addr, unsigned parity) {
    asm volatile(
        "{\n\t.reg .pred p;\n\t"
        "WL_%=:\n\t"
        "mbarrier.try_wait.parity.acquire.cluster.shared::cta.b64 p, [%0], %1;\n\t"
        "@!p bra WL_%=;\n\t}"
        :: "r"(addr), "r"(parity) : "memory");
}
__device__ __forceinline__ void clusterSync() {
    asm volatile("barrier.cluster.arrive.aligned;" ::: "memory");
    asm volatile("barrier.cluster.wait.aligned;"   ::: "memory");
}
__device__ __forceinline__ float warpAllSum(float v) {
#pragma unroll
    for (int o = 16; o; o >>= 1) v += __shfl_xor_sync(0xffffffffu, v, o);
    return v;
}
__device__ __forceinline__ float warpAllMax(float v) {
#pragma unroll
    for (int o = 16; o; o >>= 1) v = fmaxf(v, __shfl_xor_sync(0xffffffffu, v, o));
    return v;
}

// ---------------- K1: Mexp = exp(sum_k w_k f_k) with boundary masks -------
__global__ void kM(const float* __restrict__ f, const float* __restrict__ w) {
    size_t lin = ((size_t)blockIdx.x * blockDim.x + threadIdx.x) * 4;
    float w0 = __ldg(w + 0), w1 = __ldg(w + 1), w2 = __ldg(w + 2), w3 = __ldg(w + 3);
    const float4 a = *(const float4*)(f + lin);
    const float4 b = *(const float4*)(f + lin + (size_t)MAT);
    const float4 c = *(const float4*)(f + lin + 2ull * MAT);
    const float4 d = *(const float4*)(f + lin + 3ull * MAT);
    int t  = (int)(lin >> 16);
    int i  = (int)(lin >> 8) & 255;
    int j0 = (int)lin & 255;
    float v0 = w0 * a.x + w1 * b.x + w2 * c.x + w3 * d.x;
    float v1 = w0 * a.y + w1 * b.y + w2 * c.y + w3 * d.y;
    float v2 = w0 * a.z + w1 * b.z + w2 * c.z + w3 * d.z;
    float v3 = w0 * a.w + w1 * b.w + w2 * c.w + w3 * d.w;
    bool mrow = (t == 0 && i != 0);
    float4 o;
    o.x = (mrow || (t == Tt && (j0 + 0) != 0)) ? 0.f : expf(v0);
    o.y = (mrow || (t == Tt && (j0 + 1) != 0)) ? 0.f : expf(v1);
    o.z = (mrow || (t == Tt && (j0 + 2) != 0)) ? 0.f : expf(v2);
    o.w = (mrow || (t == Tt && (j0 + 3) != 0)) ? 0.f : expf(v3);
    *(float4*)(g_Mexp + lin) = o;
}

// ---------------- K2: three scans, one 8-CTA cluster each -----------------
// Exchange per step: each CTA remote-stores its 32 outputs + 1 partial to all
// 8 peers (st.shared::cluster), then ONE elected thread does 8 release-arrives.
// Each barrier counts 8 arrives per phase; double-buffered (2 barriers).
__global__ void __cluster_dims__(8, 1, 1) __launch_bounds__(256, 1) kScan() {
    __shared__ __align__(16) float sRecv[2][8 * 36];   // [buf][srcCTA*36 + 0..32]
    __shared__ float sCur[Yx];
    __shared__ float sRed[Yx];
    __shared__ int   sRedI[Yx];
    __shared__ float sInitMax;
    __shared__ __align__(16) unsigned long long mbar[2];

    const int tid  = threadIdx.x;
    const int role = blockIdx.x >> 3;
    const int rank = blockIdx.x & 7;
    const int lane = tid & 31;
    const int wid  = tid >> 5;

    const unsigned recvBase = smem_u32(&sRecv[0][0]);
    const unsigned mbarBase = smem_u32(&mbar[0]);

    if (tid == 0) { mbarInit(mbarBase, 8); mbarInit(mbarBase + 8, 8); }
    __syncthreads();
    clusterSync();                                    // peers' barriers live

    unsigned rRecv[8], rBar[8];
#pragma unroll
    for (int p = 0; p < 8; p++) {
        rRecv[p] = mapaTo(recvBase, p);
        rBar[p]  = mapaTo(mbarBase, p);
    }

    if (role == 0) {
        // ================= forward scan =================
        sCur[tid] = (tid == 0) ? 1.f : 0.f;
        if (tid < 32) g_alpha[32 * rank + tid] = (32 * rank + tid == 0) ? 1.f : 0.f;
        __syncthreads();
        const int col = 32 * rank + lane;
        const int kb  = wid * 32;
        float m[32];
        {
            const float* bp = g_Mexp + (size_t)kb * 256 + col;
#pragma unroll
            for (int k = 0; k < 32; k++) m[k] = bp[(size_t)k * 256];
        }
        for (int t = 0; t < TP1; t++) {
            const int buf = t & 1;
            float a0 = 0.f, a1 = 0.f, a2 = 0.f, a3 = 0.f;
#pragma unroll
            for (int kk = 0; kk < 32; kk += 4) {
                a0 += m[kk + 0] * sCur[kb + kk + 0];
                a1 += m[kk + 1] * sCur[kb + kk + 1];
                a2 += m[kk + 2] * sCur[kb + kk + 2];
                a3 += m[kk + 3] * sCur[kb + kk + 3];
            }
            sRed[tid] = (a0 + a1) + (a2 + a3);
            if (t + 1 < TP1) {                         // prefetch next slice
                const float* bp = g_Mexp + (size_t)(t + 1) * 65536 + (size_t)kb * 256 + col;
#pragma unroll
                for (int k = 0; k < 32; k++) m[k] = bp[(size_t)k * 256];
            }
            __syncthreads();
            if (wid == 0) {
                float raw = 0.f;
#pragma unroll
                for (int g = 0; g < 8; g++) raw += sRed[g * 32 + tid];
                float ps = warpAllSum(raw);
                unsigned off = (unsigned)(buf * 288 + rank * 36 + lane) * 4u;
#pragma unroll
                for (int p = 0; p < 8; p++) stCl(rRecv[p] + off, raw);
                if (lane == 0) {
                    unsigned po = (unsigned)(buf * 288 + rank * 36 + 32) * 4u;
#pragma unroll
                    for (int p = 0; p < 8; p++) stCl(rRecv[p] + po, ps);
                }
                __syncwarp();
                if (lane == 0) {
#pragma unroll
                    for (int p = 0; p < 8; p++) arriveRel(rBar[p] + (unsigned)buf * 8u);
                }
            }
            mbarWait(mbarBase + (unsigned)buf * 8u, (unsigned)((t >> 1) & 1));
            float s = 0.f;
#pragma unroll
            for (int p = 0; p < 8; p++) s += sRecv[buf][p * 36 + 32];
            float inv = 1.f / s;
            sCur[tid] = sRecv[buf][wid * 36 + lane] * inv;
            if (tid < 32)
                g_alpha[(size_t)(t + 1) * Yx + 32 * rank + tid] = sRecv[buf][rank * 36 + tid] * inv;
            if (rank == 0 && tid == 0) g_sA[t] = s;
            __syncthreads();
        }
    } else if (role == 1) {
        // ================= backward scan =================
        sCur[tid] = (tid == 0) ? 1.f : 0.f;
        if (tid < 32) g_beta[(size_t)513 * Yx + 32 * rank + tid] = (32 * rank + tid == 0) ? 1.f : 0.f;
        __syncthreads();
        const int rbase = 32 * rank + wid * 4;
        float m[32];
        {
            const float* bp = g_Mexp + (size_t)Tt * 65536 + (size_t)rbase * 256 + lane;
#pragma unroll
            for (int c = 0; c < 4; c++)
#pragma unroll
                for (int jb = 0; jb < 8; jb++) m[c * 8 + jb] = bp[(size_t)c * 256 + jb * 32];
        }
        for (int idx = 0; idx < TP1; idx++) {
            const int t = Tt - idx;
            const int buf = idx & 1;
            float a0 = 0.f, a1 = 0.f, a2 = 0.f, a3 = 0.f;
#pragma unroll
            for (int jb = 0; jb < 8; jb++) {
                float cv = sCur[jb * 32 + lane];
                a0 += m[0 * 8 + jb] * cv;
                a1 += m[1 * 8 + jb] * cv;
                a2 += m[2 * 8 + jb] * cv;
                a3 += m[3 * 8 + jb] * cv;
            }
            a0 = warpAllSum(a0); a1 = warpAllSum(a1);
            a2 = warpAllSum(a2); a3 = warpAllSum(a3);
            if (lane < 4) {     // remote-store this warp's 4 row results to all peers
                float v = (lane == 0) ? a0 : (lane == 1) ? a1 : (lane == 2) ? a2 : a3;
                unsigned off = (unsigned)(buf * 288 + rank * 36 + wid * 4 + lane) * 4u;
#pragma unroll
                for (int p = 0; p < 8; p++) stCl(rRecv[p] + off, v);
            }
            if (lane == 0) sRed[wid] = (a0 + a1) + (a2 + a3);
            if (t - 1 >= 0) {                          // prefetch next slice
                const float* bp = g_Mexp + (size_t)(t - 1) * 65536 + (size_t)rbase * 256 + lane;
#pragma unroll
                for (int c = 0; c < 4; c++)
#pragma unroll
                    for (int jb = 0; jb < 8; jb++) m[c * 8 + jb] = bp[(size_t)c * 256 + jb * 32];
            }
            __syncthreads();
            if (tid == 0) {
                float ps = 0.f;
#pragma unroll
                for (int g = 0; g < 8; g++) ps += sRed[g];
                unsigned po = (unsigned)(buf * 288 + rank * 36 + 32) * 4u;
#pragma unroll
                for (int p = 0; p < 8; p++) stCl(rRecv[p] + po, ps);
#pragma unroll
                for (int p = 0; p < 8; p++) arriveRel(rBar[p] + (unsigned)buf * 8u);
            }
            mbarWait(mbarBase + (unsigned)buf * 8u, (unsigned)((idx >> 1) & 1));
            float s = 0.f;
#pragma unroll
            for (int p = 0; p < 8; p++) s += sRecv[buf][p * 36 + 32];
            float inv = 1.f / s;
            sCur[tid] = sRecv[buf][wid * 36 + lane] * inv;
            if (tid < 32)
                g_beta[(size_t)t * Yx + 32 * rank + tid] = sRecv[buf][rank * 36 + tid] * inv;
            if (rank == 0 && tid == 0) g_sB[t] = s;
            __syncthreads();
        }
    } else {
        // ================= viterbi (max-times) =================
        float v0 = g_Mexp[tid];                        // Mexp[0][0][:]
        sRed[tid] = v0;
        __syncthreads();
        if (wid == 0) {
            float mx = sRed[tid];
#pragma unroll
            for (int g = 1; g < 8; g++) mx = fmaxf(mx, sRed[g * 32 + tid]);
            mx = warpAllMax(mx);
            if (tid == 0) sInitMax = mx;
        }
        __syncthreads();
        sCur[tid] = v0 / sInitMax;
        __syncthreads();
        const int col = 32 * rank + lane;
        const int kb  = wid * 32;
        float m[32];
        {
            const float* bp = g_Mexp + (size_t)65536 + (size_t)kb * 256 + col;
#pragma unroll
            for (int k = 0; k < 32; k++) m[k] = bp[(size_t)k * 256];
        }
        for (int t = 1; t < Tt; t++) {
            const int idx = t - 1;
            const int buf = idx & 1;
            float best = -1.f; int bidx = 0;
#pragma unroll
            for (int k = 0; k < 32; k++) {
                float p = m[k] * sCur[kb + k];
                if (p > best) { best = p; bidx = kb + k; }   // strict >: lowest index wins
            }
            sRed[tid] = best; sRedI[tid] = bidx;
            if (t + 1 < Tt) {
                const float* bp = g_Mexp + (size_t)(t + 1) * 65536 + (size_t)kb * 256 + col;
#pragma unroll
                for (int k = 0; k < 32; k++) m[k] = bp[(size_t)k * 256];
            }
            __syncthreads();
            if (wid == 0) {
                float b = sRed[tid]; int ix = sRedI[tid];
#pragma unroll
                for (int g = 1; g < 8; g++) {
                    float vv = sRed[g * 32 + tid];
                    if (vv > b) { b = vv; ix = sRedI[g * 32 + tid]; }
                }
                g_idx[(size_t)idx * Yx + 32 * rank + tid] = (unsigned char)ix;
                float pm = warpAllMax(b);
                unsigned off = (unsigned)(buf * 288 + rank * 36 + lane) * 4u;
#pragma unroll
                for (int p = 0; p < 8; p++) stCl(rRecv[p] + off, b);
                if (lane == 0) {
                    unsigned po = (unsigned)(buf * 288 + rank * 36 + 32) * 4u;
#pragma unroll
                    for (int p = 0; p < 8; p++) stCl(rRecv[p] + po, pm);
                }
                __syncwarp();
                if (lane == 0) {
#pragma unroll
                    for (int p = 0; p < 8; p++) arriveRel(rBar[p] + (unsigned)buf * 8u);
                }
            }
            mbarWait(mbarBase + (unsigned)buf * 8u, (unsigned)((idx >> 1) & 1));
            float s = sRecv[buf][0 * 36 + 32];
#pragma unroll
            for (int p = 1; p < 8; p++) s = fmaxf(s, sRecv[buf][p * 36 + 32]);
            float inv = 1.f / s;
            sCur[tid] = sRecv[buf][wid * 36 + lane] * inv;   // uniform scale: argmax preserved
            __syncthreads();
        }
        if (rank == 0) g_dfin[tid] = sCur[tid];
    }
    clusterSync();   // no CTA exits while peers may still store into it
}

// ---------------- K3: log-scale prefix sums (double), F, backtrack --------
extern __shared__ unsigned char sdyn[];
__global__ void kFinish(float* __restrict__ dout, int writePath) {
    double* sLA = (double*)sdyn;                        // [514]
    double* sLB = sLA + 514;                            // [514]
    unsigned char* sIdx = (unsigned char*)(sLB + 514);  // [511*256]
    int tid = threadIdx.x;

    {
        const uint4* src = (const uint4*)g_idx;
        uint4* dst = (uint4*)sIdx;
        for (int i = tid; i < (511 * 256) / 16; i += 256) dst[i] = src[i];
    }
    for (int t = tid; t < 513; t += 256) {
        sLA[t + 1] = log((double)g_sA[t]);
        sLB[t]     = log((double)g_sB[t]);
    }
    if (tid == 0) { sLA[0] = 0.0; sLB[513] = 0.0; }
    __syncthreads();
    if (tid == 0) {            // LA prefix sum
        double r = 0.0;
        for (int t = 1; t <= 513; t++) { r += sLA[t]; sLA[t] = r; }
    } else if (tid == 32) {    // LB suffix sum
        double r = 0.0;
        for (int t = 512; t >= 0; t--) { r += sLB[t]; sLB[t] = r; }
    } else if (tid == 64 && writePath) {  // backtrack (runs concurrently)
        float best = g_dfin[0]; int last = 0;
        for (int j = 1; j < 256; j++) { float v = g_dfin[j]; if (v > best) { best = v; last = j; } }
        float* pout = dout + (size_t)MAT;
        pout[511] = (float)last;
        int y = last;
        for (int r = 510; r >= 0; r--) { y = sIdx[r * 256 + y]; pout[r] = (float)y; }
    }
    __syncthreads();
    double lz = sLA[513];
    for (int t = tid; t < 513; t += 256)
        g_F[t] = expf((float)(sLA[t] + sLB[t + 1] - lz));
}

// ---------------- K4: p12 = alpha[t][i]*F[t] * Mexp * beta[t+1][j] --------
__global__ void kP12(float* __restrict__ dout) {
    size_t lin = ((size_t)blockIdx.x * blockDim.x + threadIdx.x) * 4;
    int t = (int)(lin >> 16);
    int i = (int)(lin >> 8) & 255;
    int j = (int)lin & 255;
    float4 mv = *(const float4*)(g_Mexp + lin);
    float  a  = g_alpha[t * 256 + i] * __ldg(g_F + t);
    float4 bv = *(const float4*)(g_beta + (size_t)(t + 1) * 256 + j);
    float4 o;
    o.x = a * mv.x * bv.x;
    o.y = a * mv.y * bv.y;
    o.z = a * mv.z * bv.z;
    o.w = a * mv.w * bv.w;
    *(float4*)(dout + lin) = o;
}

// ---------------- launch ---------------------------------------------------
extern "C" void kernel_launch(void* const* d_in, const int* in_sizes, int n_in,
                              void* d_out, int out_size) {
    const float* f = (const float*)d_in[0];
    const float* w = (const float*)d_in[1];
    if (n_in >= 2 && in_sizes[0] == 4) {
        f = (const float*)d_in[1];
        w = (const float*)d_in[0];
    }
    float* out = (float*)d_out;
    int writePath = (out_size >= MAT + 512) ? 1 : 0;

    const int FIN_SMEM = 514 * 8 * 2 + 511 * 256;  // 139,040 B
    cudaFuncSetAttribute(kFinish, cudaFuncAttributeMaxDynamicSharedMemorySize, FIN_SMEM);

    kM<<<32832, 256>>>(f, w);
    kScan<<<24, 256>>>();
    kFinish<<<1, 256, FIN_SMEM>>>(out, writePath);
    kP12<<<32832, 256>>>(out);
}

// round 8
// speedup vs baseline: 2.7544x; 2.2470x over previous
#include <cuda_runtime.h>
#include <cstdint>
#include <math.h>

#define Yx   256
#define TP1  513
#define Tt   512
#define MAT  (TP1 * Yx * Yx)   // 33,619,968

// ---------------- scratch (static device globals; no allocation) ----------
__device__ __align__(16) float g_Mexp[MAT];
__device__ float g_alpha[(TP1 + 1) * Yx];
__device__ float g_beta [(TP1 + 1) * Yx];
__device__ float g_sA[TP1];
__device__ float g_sB[TP1];
__device__ float g_F[TP1];                              // exp(LA[t]+LB[t+1]-logZ)
__device__ __align__(16) unsigned char g_idx[(Tt - 1) * Yx];
__device__ float g_dfin[Yx];

// ---------------- helpers -------------------------------------------------
__device__ __forceinline__ unsigned smem_u32(const void* p) {
    return (unsigned)__cvta_generic_to_shared(p);
}
__device__ __forceinline__ unsigned mapaTo(unsigned saddr, unsigned peer) {
    unsigned ra;
    asm volatile("mapa.shared::cluster.u32 %0, %1, %2;" : "=r"(ra) : "r"(saddr), "r"(peer));
    return ra;
}
// single 8B remote store: (tag<<32 | value) — atomically visible, self-synchronizing
__device__ __forceinline__ void stCl64(unsigned ra, unsigned long long v) {
    asm volatile("st.shared::cluster.b64 [%0], %1;" :: "r"(ra), "l"(v) : "memory");
}
__device__ __forceinline__ unsigned long long packTV(unsigned tag, float v) {
    return ((unsigned long long)tag << 32) | (unsigned long long)__float_as_uint(v);
}
__device__ __forceinline__ float slotVal(const unsigned long long* s) {
    return __uint_as_float(*(const unsigned*)s);        // low 4 bytes
}
__device__ __forceinline__ void clusterSync() {
    asm volatile("barrier.cluster.arrive.aligned;" ::: "memory");
    asm volatile("barrier.cluster.wait.aligned;"   ::: "memory");
}
__device__ __forceinline__ float warpAllSum(float v) {
#pragma unroll
    for (int o = 16; o; o >>= 1) v += __shfl_xor_sync(0xffffffffu, v, o);
    return v;
}
__device__ __forceinline__ float warpAllMax(float v) {
#pragma unroll
    for (int o = 16; o; o >>= 1) v = fmaxf(v, __shfl_xor_sync(0xffffffffu, v, o));
    return v;
}
// warp-0 collective poll: wait until all 8 srcs' 33 slot tags == tag.
// sRecvBuf points at sRecv[buf][0][0] (stride 34 u64 per src).
__device__ __forceinline__ void pollTags(const unsigned long long* sRecvBuf,
                                         unsigned tag, int lane) {
    const volatile unsigned* b = (const volatile unsigned*)sRecvBuf;
    const int src = lane >> 2;       // 4 lanes per src CTA
    const int s0  = lane & 3;        // each checks slots s0, s0+4, ..., <33
    for (;;) {
        bool ok = true;
#pragma unroll
        for (int i = 0; i < 9; i++) {
            int s = s0 + i * 4;
            if (s < 33) ok &= (b[(src * 34 + s) * 2 + 1] == tag);
        }
        if (__all_sync(0xffffffffu, ok)) break;
    }
}

// ---------------- K1: Mexp = exp(sum_k w_k f_k) with boundary masks -------
__global__ void kM(const float* __restrict__ f, const float* __restrict__ w) {
    size_t lin = ((size_t)blockIdx.x * blockDim.x + threadIdx.x) * 4;
    float w0 = __ldg(w + 0), w1 = __ldg(w + 1), w2 = __ldg(w + 2), w3 = __ldg(w + 3);
    const float4 a = *(const float4*)(f + lin);
    const float4 b = *(const float4*)(f + lin + (size_t)MAT);
    const float4 c = *(const float4*)(f + lin + 2ull * MAT);
    const float4 d = *(const float4*)(f + lin + 3ull * MAT);
    int t  = (int)(lin >> 16);
    int i  = (int)(lin >> 8) & 255;
    int j0 = (int)lin & 255;
    float v0 = w0 * a.x + w1 * b.x + w2 * c.x + w3 * d.x;
    float v1 = w0 * a.y + w1 * b.y + w2 * c.y + w3 * d.y;
    float v2 = w0 * a.z + w1 * b.z + w2 * c.z + w3 * d.z;
    float v3 = w0 * a.w + w1 * b.w + w2 * c.w + w3 * d.w;
    bool mrow = (t == 0 && i != 0);
    float4 o;
    o.x = (mrow || (t == Tt && (j0 + 0) != 0)) ? 0.f : expf(v0);
    o.y = (mrow || (t == Tt && (j0 + 1) != 0)) ? 0.f : expf(v1);
    o.z = (mrow || (t == Tt && (j0 + 2) != 0)) ? 0.f : expf(v2);
    o.w = (mrow || (t == Tt && (j0 + 3) != 0)) ? 0.f : expf(v3);
    *(float4*)(g_Mexp + lin) = o;
}

// ---------------- K2: three scans, one 8-CTA cluster each -----------------
// Exchange: every value is an 8B (tag,value) remote store; receiver polls the
// tags locally with warp 0 and releases the CTA via __syncthreads. No
// mbarriers, no fences, no cluster barrier inside the loop.
__global__ void __cluster_dims__(8, 1, 1) __launch_bounds__(256, 1) kScan() {
    __shared__ __align__(16) unsigned long long sRecv[2][8][34]; // [buf][src][slot] 0..31 vals, 32 partial
    __shared__ float sCur[Yx];
    __shared__ float sRed[Yx];
    __shared__ int   sRedI[Yx];
    __shared__ float sInitMax;

    const int tid  = threadIdx.x;
    const int role = blockIdx.x >> 3;
    const int rank = blockIdx.x & 7;
    const int lane = tid & 31;
    const int wid  = tid >> 5;

    const unsigned recvBase = smem_u32(&sRecv[0][0][0]);

    // zero tags in both buffers
    for (int i = tid; i < 2 * 8 * 34; i += 256) ((unsigned long long*)sRecv)[i] = 0ull;
    __syncthreads();
    clusterSync();                                    // peers' buffers zeroed

    unsigned rRecv[8];
#pragma unroll
    for (int p = 0; p < 8; p++) rRecv[p] = mapaTo(recvBase, p);

    if (role == 0) {
        // ================= forward scan =================
        sCur[tid] = (tid == 0) ? 1.f : 0.f;
        if (tid < 32) g_alpha[32 * rank + tid] = (32 * rank + tid == 0) ? 1.f : 0.f;
        __syncthreads();
        const int col = 32 * rank + lane;
        const int kb  = wid * 32;
        float m[32];
        {
            const float* bp = g_Mexp + (size_t)kb * 256 + col;
#pragma unroll
            for (int k = 0; k < 32; k++) m[k] = bp[(size_t)k * 256];
        }
        for (int t = 0; t < TP1; t++) {
            const int buf = t & 1;
            const unsigned tag = (unsigned)(t + 1);
            float a0 = 0.f, a1 = 0.f, a2 = 0.f, a3 = 0.f;
#pragma unroll
            for (int kk = 0; kk < 32; kk += 4) {
                a0 += m[kk + 0] * sCur[kb + kk + 0];
                a1 += m[kk + 1] * sCur[kb + kk + 1];
                a2 += m[kk + 2] * sCur[kb + kk + 2];
                a3 += m[kk + 3] * sCur[kb + kk + 3];
            }
            sRed[tid] = (a0 + a1) + (a2 + a3);
            if (t + 1 < TP1) {                         // prefetch next slice
                const float* bp = g_Mexp + (size_t)(t + 1) * 65536 + (size_t)kb * 256 + col;
#pragma unroll
                for (int k = 0; k < 32; k++) m[k] = bp[(size_t)k * 256];
            }
            __syncthreads();
            if (wid == 0) {
                float raw = 0.f;
#pragma unroll
                for (int g = 0; g < 8; g++) raw += sRed[g * 32 + tid];
                float ps = warpAllSum(raw);
                unsigned long long pkv = packTV(tag, raw);
                unsigned off = (unsigned)((buf * 272 + rank * 34 + lane) * 8);
#pragma unroll
                for (int p = 0; p < 8; p++) stCl64(rRecv[p] + off, pkv);
                if (lane == 0) {
                    unsigned long long pps = packTV(tag, ps);
                    unsigned po = (unsigned)((buf * 272 + rank * 34 + 32) * 8);
#pragma unroll
                    for (int p = 0; p < 8; p++) stCl64(rRecv[p] + po, pps);
                }
                pollTags(&sRecv[buf][0][0], tag, lane);
            }
            __syncthreads();
            float s = 0.f;
#pragma unroll
            for (int p = 0; p < 8; p++) s += slotVal(&sRecv[buf][p][32]);
            float inv = 1.f / s;
            sCur[tid] = slotVal(&sRecv[buf][wid][lane]) * inv;
            if (tid < 32)
                g_alpha[(size_t)(t + 1) * Yx + 32 * rank + tid] = slotVal(&sRecv[buf][rank][tid]) * inv;
            if (rank == 0 && tid == 0) g_sA[t] = s;
            __syncthreads();
        }
    } else if (role == 1) {
        // ================= backward scan =================
        sCur[tid] = (tid == 0) ? 1.f : 0.f;
        if (tid < 32) g_beta[(size_t)513 * Yx + 32 * rank + tid] = (32 * rank + tid == 0) ? 1.f : 0.f;
        __syncthreads();
        const int rbase = 32 * rank + wid * 4;
        float m[32];
        {
            const float* bp = g_Mexp + (size_t)Tt * 65536 + (size_t)rbase * 256 + lane;
#pragma unroll
            for (int c = 0; c < 4; c++)
#pragma unroll
                for (int jb = 0; jb < 8; jb++) m[c * 8 + jb] = bp[(size_t)c * 256 + jb * 32];
        }
        for (int idx = 0; idx < TP1; idx++) {
            const int t = Tt - idx;
            const int buf = idx & 1;
            const unsigned tag = (unsigned)(idx + 1);
            float a0 = 0.f, a1 = 0.f, a2 = 0.f, a3 = 0.f;
#pragma unroll
            for (int jb = 0; jb < 8; jb++) {
                float cv = sCur[jb * 32 + lane];
                a0 += m[0 * 8 + jb] * cv;
                a1 += m[1 * 8 + jb] * cv;
                a2 += m[2 * 8 + jb] * cv;
                a3 += m[3 * 8 + jb] * cv;
            }
            a0 = warpAllSum(a0); a1 = warpAllSum(a1);
            a2 = warpAllSum(a2); a3 = warpAllSum(a3);
            if (lane < 4) {     // each warp ships its 4 row results immediately
                float v = (lane == 0) ? a0 : (lane == 1) ? a1 : (lane == 2) ? a2 : a3;
                unsigned long long pkv = packTV(tag, v);
                unsigned off = (unsigned)((buf * 272 + rank * 34 + wid * 4 + lane) * 8);
#pragma unroll
                for (int p = 0; p < 8; p++) stCl64(rRecv[p] + off, pkv);
            }
            if (lane == 0) sRed[wid] = (a0 + a1) + (a2 + a3);
            if (t - 1 >= 0) {                          // prefetch next slice
                const float* bp = g_Mexp + (size_t)(t - 1) * 65536 + (size_t)rbase * 256 + lane;
#pragma unroll
                for (int c = 0; c < 4; c++)
#pragma unroll
                    for (int jb = 0; jb < 8; jb++) m[c * 8 + jb] = bp[(size_t)c * 256 + jb * 32];
            }
            __syncthreads();
            if (wid == 0) {
                if (lane == 0) {
                    float ps = 0.f;
#pragma unroll
                    for (int g = 0; g < 8; g++) ps += sRed[g];
                    unsigned long long pps = packTV(tag, ps);
                    unsigned po = (unsigned)((buf * 272 + rank * 34 + 32) * 8);
#pragma unroll
                    for (int p = 0; p < 8; p++) stCl64(rRecv[p] + po, pps);
                }
                pollTags(&sRecv[buf][0][0], tag, lane);
            }
            __syncthreads();
            float s = 0.f;
#pragma unroll
            for (int p = 0; p < 8; p++) s += slotVal(&sRecv[buf][p][32]);
            float inv = 1.f / s;
            sCur[tid] = slotVal(&sRecv[buf][wid][lane]) * inv;
            if (tid < 32)
                g_beta[(size_t)t * Yx + 32 * rank + tid] = slotVal(&sRecv[buf][rank][tid]) * inv;
            if (rank == 0 && tid == 0) g_sB[t] = s;
            __syncthreads();
        }
    } else {
        // ================= viterbi (max-times) =================
        float v0 = g_Mexp[tid];                        // Mexp[0][0][:]
        sRed[tid] = v0;
        __syncthreads();
        if (wid == 0) {
            float mx = sRed[tid];
#pragma unroll
            for (int g = 1; g < 8; g++) mx = fmaxf(mx, sRed[g * 32 + tid]);
            mx = warpAllMax(mx);
            if (tid == 0) sInitMax = mx;
        }
        __syncthreads();
        sCur[tid] = v0 / sInitMax;
        __syncthreads();
        const int col = 32 * rank + lane;
        const int kb  = wid * 32;
        float m[32];
        {
            const float* bp = g_Mexp + (size_t)65536 + (size_t)kb * 256 + col;
#pragma unroll
            for (int k = 0; k < 32; k++) m[k] = bp[(size_t)k * 256];
        }
        for (int t = 1; t < Tt; t++) {
            const int idx = t - 1;
            const int buf = idx & 1;
            const unsigned tag = (unsigned)t;          // >= 1
            float best = -1.f; int bidx = 0;
#pragma unroll
            for (int k = 0; k < 32; k++) {
                float p = m[k] * sCur[kb + k];
                if (p > best) { best = p; bidx = kb + k; }   // strict >: lowest index wins
            }
            sRed[tid] = best; sRedI[tid] = bidx;
            if (t + 1 < Tt) {
                const float* bp = g_Mexp + (size_t)(t + 1) * 65536 + (size_t)kb * 256 + col;
#pragma unroll
                for (int k = 0; k < 32; k++) m[k] = bp[(size_t)k * 256];
            }
            __syncthreads();
            if (wid == 0) {
                float b = sRed[tid]; int ix = sRedI[tid];
#pragma unroll
                for (int g = 1; g < 8; g++) {
                    float vv = sRed[g * 32 + tid];
                    if (vv > b) { b = vv; ix = sRedI[g * 32 + tid]; }
                }
                g_idx[(size_t)idx * Yx + 32 * rank + tid] = (unsigned char)ix;
                float pm = warpAllMax(b);
                unsigned long long pkv = packTV(tag, b);
                unsigned off = (unsigned)((buf * 272 + rank * 34 + lane) * 8);
#pragma unroll
                for (int p = 0; p < 8; p++) stCl64(rRecv[p] + off, pkv);
                if (lane == 0) {
                    unsigned long long pps = packTV(tag, pm);
                    unsigned po = (unsigned)((buf * 272 + rank * 34 + 32) * 8);
#pragma unroll
                    for (int p = 0; p < 8; p++) stCl64(rRecv[p] + po, pps);
                }
                pollTags(&sRecv[buf][0][0], tag, lane);
            }
            __syncthreads();
            float s = slotVal(&sRecv[buf][0][32]);
#pragma unroll
            for (int p = 1; p < 8; p++) s = fmaxf(s, slotVal(&sRecv[buf][p][32]));
            float inv = 1.f / s;
            sCur[tid] = slotVal(&sRecv[buf][wid][lane]) * inv;   // uniform scale: argmax kept
            __syncthreads();
        }
        if (rank == 0) g_dfin[tid] = sCur[tid];
    }
    clusterSync();   // no CTA exits while peers may still store into it
}

// ---------------- K3: log-scale prefix sums (double), F, backtrack --------
extern __shared__ unsigned char sdyn[];
__global__ void kFinish(float* __restrict__ dout, int writePath) {
    double* sLA = (double*)sdyn;                        // [514]
    double* sLB = sLA + 514;                            // [514]
    unsigned char* sIdx = (unsigned char*)(sLB + 514);  // [511*256]
    int tid = threadIdx.x;

    {
        const uint4* src = (const uint4*)g_idx;
        uint4* dst = (uint4*)sIdx;
        for (int i = tid; i < (511 * 256) / 16; i += 256) dst[i] = src[i];
    }
    for (int t = tid; t < 513; t += 256) {
        sLA[t + 1] = log((double)g_sA[t]);
        sLB[t]     = log((double)g_sB[t]);
    }
    if (tid == 0) { sLA[0] = 0.0; sLB[513] = 0.0; }
    __syncthreads();
    if (tid == 0) {            // LA prefix sum
        double r = 0.0;
        for (int t = 1; t <= 513; t++) { r += sLA[t]; sLA[t] = r; }
    } else if (tid == 32) {    // LB suffix sum
        double r = 0.0;
        for (int t = 512; t >= 0; t--) { r += sLB[t]; sLB[t] = r; }
    } else if (tid == 64 && writePath) {  // backtrack (runs concurrently)
        float best = g_dfin[0]; int last = 0;
        for (int j = 1; j < 256; j++) { float v = g_dfin[j]; if (v > best) { best = v; last = j; } }
        float* pout = dout + (size_t)MAT;
        pout[511] = (float)last;
        int y = last;
        for (int r = 510; r >= 0; r--) { y = sIdx[r * 256 + y]; pout[r] = (float)y; }
    }
    __syncthreads();
    double lz = sLA[513];
    for (int t = tid; t < 513; t += 256)
        g_F[t] = expf((float)(sLA[t] + sLB[t + 1] - lz));
}

// ---------------- K4: p12 = alpha[t][i]*F[t] * Mexp * beta[t+1][j] --------
__global__ void kP12(float* __restrict__ dout) {
    size_t lin = ((size_t)blockIdx.x * blockDim.x + threadIdx.x) * 4;
    int t = (int)(lin >> 16);
    int i = (int)(lin >> 8) & 255;
    int j = (int)lin & 255;
    float4 mv = *(const float4*)(g_Mexp + lin);
    float  a  = g_alpha[t * 256 + i] * __ldg(g_F + t);
    float4 bv = *(const float4*)(g_beta + (size_t)(t + 1) * 256 + j);
    float4 o;
    o.x = a * mv.x * bv.x;
    o.y = a * mv.y * bv.y;
    o.z = a * mv.z * bv.z;
    o.w = a * mv.w * bv.w;
    *(float4*)(dout + lin) = o;
}

// ---------------- launch ---------------------------------------------------
extern "C" void kernel_launch(void* const* d_in, const int* in_sizes, int n_in,
                              void* d_out, int out_size) {
    const float* f = (const float*)d_in[0];
    const float* w = (const float*)d_in[1];
    if (n_in >= 2 && in_sizes[0] == 4) {
        f = (const float*)d_in[1];
        w = (const float*)d_in[0];
    }
    float* out = (float*)d_out;
    int writePath = (out_size >= MAT + 512) ? 1 : 0;

    const int FIN_SMEM = 514 * 8 * 2 + 511 * 256;  // 139,040 B
    cudaFuncSetAttribute(kFinish, cudaFuncAttributeMaxDynamicSharedMemorySize, FIN_SMEM);

    kM<<<32832, 256>>>(f, w);
    kScan<<<24, 256>>>();
    kFinish<<<1, 256, FIN_SMEM>>>(out, writePath);
    kP12<<<32832, 256>>>(out);
}